// round 11
// baseline (speedup 1.0000x reference)
#include <cuda_runtime.h>

#define NC   21
#define NC2  (NC * NC)
#define NB   8
#define HW   (512 * 512)
#define Q    (HW / 4)            // float4 groups per channel plane (65536)
#define TPB  512
#define NBLOCKS 296              // 2 CTAs per SM, all resident: zero tail
#define NWT  16384               // total warp-tiles (32 groups = 512 B each)
#define WT_BASE (NWT / NBLOCKS)  // 55
#define WT_REM  (NWT % NBLOCKS)  // 104 blocks get one extra warp-tile

// Scratch: per-sample confusion matrices conf[b][true][pred].
// Zero at module load; the last block of each invocation re-zeroes after use.
__device__ int g_conf[NB * NC2];
__device__ unsigned int g_done;   // zero-init; reset by last block each run

__global__ void __launch_bounds__(TPB, 2)
conf_kernel(const float* __restrict__ pred,
            const float* __restrict__ tgt,
            float* __restrict__ out) {
    __shared__ int sconf[2][NC2];   // two banks: chunk may straddle 1 sample boundary
    for (int i = threadIdx.x; i < 2 * NC2; i += TPB) (&sconf[0][0])[i] = 0;
    __syncthreads();

    const int j = blockIdx.x;
    const int wt = WT_BASE + (j < WT_REM ? 1 : 0);
    const int start = 32 * (j * WT_BASE + (j < WT_REM ? j : WT_REM));
    const int end = start + wt * 32;    // contiguous group range [start, end)

    for (int base = start; base < end; base += TPB) {
        int g = base + threadIdx.x;
        if (g < end) {
            int b = g >> 16;            // Q = 65536
            int p = g & (Q - 1);

            const float4* pp = reinterpret_cast<const float4*>(pred) + (size_t)b * NC * Q + p;
            const float4* tp = reinterpret_cast<const float4*>(tgt)  + (size_t)b * NC * Q + p;

            float4 pm = __ldcs(pp);
            float4 tm = __ldcs(tp);
            int pax = 0, pay = 0, paz = 0, paw = 0;
            int tax = 0, tay = 0, taz = 0, taw = 0;

            #pragma unroll
            for (int c = 1; c < NC; c++) {
                float4 v = __ldcs(pp + (size_t)c * Q);
                float4 w = __ldcs(tp + (size_t)c * Q);
                if (v.x > pm.x) { pm.x = v.x; pax = c; }
                if (v.y > pm.y) { pm.y = v.y; pay = c; }
                if (v.z > pm.z) { pm.z = v.z; paz = c; }
                if (v.w > pm.w) { pm.w = v.w; paw = c; }
                if (w.x > tm.x) { tm.x = w.x; tax = c; }
                if (w.y > tm.y) { tm.y = w.y; tay = c; }
                if (w.z > tm.z) { tm.z = w.z; taz = c; }
                if (w.w > tm.w) { tm.w = w.w; taw = c; }
            }

            int* sc = sconf[b & 1];
            atomicAdd(&sc[tax * NC + pax], 1);
            atomicAdd(&sc[tay * NC + pay], 1);
            atomicAdd(&sc[taz * NC + paz], 1);
            atomicAdd(&sc[taw * NC + paw], 1);
        }
    }

    __syncthreads();

    // Flush: map banks back to the (at most two) samples this block touched.
    const int b_lo = start >> 16;
    const int b_hi = (end - 1) >> 16;
    for (int i = threadIdx.x; i < NC2; i += TPB) {
        int v = sconf[b_lo & 1][i];
        if (v) atomicAdd(&g_conf[b_lo * NC2 + i], v);
        if (b_hi != b_lo) {
            int v2 = sconf[b_hi & 1][i];
            if (v2) atomicAdd(&g_conf[b_hi * NC2 + i], v2);
        }
    }

    // ---- last-block finalize ----
    __threadfence();
    __shared__ unsigned int s_rank;
    if (threadIdx.x == 0) s_rank = atomicAdd(&g_done, 1u);
    __syncthreads();
    if (s_rank != NBLOCKS - 1) return;

    __shared__ float iou_sum[NB];
    __shared__ int   valid_cnt[NB];
    int t = threadIdx.x;
    if (t < NB) { iou_sum[t] = 0.0f; valid_cnt[t] = 0; }
    if (t == 0) g_done = 0;                 // reset for next invocation
    __syncthreads();

    if (t < NB * NC) {
        int bb = t / NC;
        int c  = t - bb * NC;
        const int* cb = &g_conf[bb * NC2];
        int tpv = __ldcg(&cb[c * NC + c]);
        int row = 0, col = 0;
        #pragma unroll
        for (int k = 0; k < NC; k++) {
            row += __ldcg(&cb[c * NC + k]);   // TP + FN
            col += __ldcg(&cb[k * NC + c]);   // TP + FP
        }
        if (tpv > 0) {
            float iou = (float)tpv / (float)(row + col - tpv);
            atomicAdd(&iou_sum[bb], iou);
            atomicAdd(&valid_cnt[bb], 1);
        }
    }
    __syncthreads();

    // Re-zero scratch for the next invocation (all reads done above).
    for (int i = t; i < NB * NC2; i += TPB) g_conf[i] = 0;

    if (t == 0) {
        float s = 0.0f;
        #pragma unroll
        for (int bb = 0; bb < NB; bb++)
            s += iou_sum[bb] / fmaxf((float)valid_cnt[bb], 1.0f);
        out[0] = s / (float)NB;
    }
}

extern "C" void kernel_launch(void* const* d_in, const int* in_sizes, int n_in,
                              void* d_out, int out_size) {
    const float* pred = (const float*)d_in[0];
    const float* tgt  = (const float*)d_in[1];
    float* out = (float*)d_out;

    conf_kernel<<<NBLOCKS, TPB>>>(pred, tgt, out);
}

// round 12
// speedup vs baseline: 1.0090x; 1.0090x over previous
#include <cuda_runtime.h>

#define NC   21
#define NC2  (NC * NC)
#define NB   8
#define HW   (512 * 512)
#define Q    (HW / 4)            // float4 groups per channel plane (65536)
#define TPB  512
#define NBLOCKS 296              // 2 CTAs per SM, all resident: zero tail
#define NWT  16384               // total warp-tiles (32 groups = 512 B each)
#define WT_BASE (NWT / NBLOCKS)  // 55
#define WT_REM  (NWT % NBLOCKS)  // 104 blocks get one extra warp-tile

// Scratch: per-sample confusion matrices conf[b][true][pred].
// Zero at module load; the last block of each invocation re-zeroes after use.
__device__ int g_conf[NB * NC2];
__device__ unsigned int g_done;   // zero-init; reset by last block each run

// Streaming load with 256B L2 prefetch: evict-first AND ask the L2/MC to pull
// a full 256B granule per request (stream is perfectly sequential, so the
// second 128B is always consumed — pure request-count reduction).
__device__ __forceinline__ float4 ldcs256(const float4* p) {
    float4 v;
    asm volatile("ld.global.cs.L2::256B.v4.f32 {%0,%1,%2,%3}, [%4];"
                 : "=f"(v.x), "=f"(v.y), "=f"(v.z), "=f"(v.w)
                 : "l"(p));
    return v;
}

__global__ void __launch_bounds__(TPB, 2)
conf_kernel(const float* __restrict__ pred,
            const float* __restrict__ tgt,
            float* __restrict__ out) {
    __shared__ int sconf[2][NC2];   // two banks: chunk may straddle 1 sample boundary
    for (int i = threadIdx.x; i < 2 * NC2; i += TPB) (&sconf[0][0])[i] = 0;
    __syncthreads();

    const int j = blockIdx.x;
    const int wt = WT_BASE + (j < WT_REM ? 1 : 0);
    const int start = 32 * (j * WT_BASE + (j < WT_REM ? j : WT_REM));
    const int end = start + wt * 32;    // contiguous group range [start, end)

    for (int base = start; base < end; base += TPB) {
        int g = base + threadIdx.x;
        if (g < end) {
            int b = g >> 16;            // Q = 65536
            int p = g & (Q - 1);

            const float4* pp = reinterpret_cast<const float4*>(pred) + (size_t)b * NC * Q + p;
            const float4* tp = reinterpret_cast<const float4*>(tgt)  + (size_t)b * NC * Q + p;

            float4 pm = ldcs256(pp);
            float4 tm = ldcs256(tp);
            int pax = 0, pay = 0, paz = 0, paw = 0;
            int tax = 0, tay = 0, taz = 0, taw = 0;

            #pragma unroll
            for (int c = 1; c < NC; c++) {
                float4 v = ldcs256(pp + (size_t)c * Q);
                float4 w = ldcs256(tp + (size_t)c * Q);
                if (v.x > pm.x) { pm.x = v.x; pax = c; }
                if (v.y > pm.y) { pm.y = v.y; pay = c; }
                if (v.z > pm.z) { pm.z = v.z; paz = c; }
                if (v.w > pm.w) { pm.w = v.w; paw = c; }
                if (w.x > tm.x) { tm.x = w.x; tax = c; }
                if (w.y > tm.y) { tm.y = w.y; tay = c; }
                if (w.z > tm.z) { tm.z = w.z; taz = c; }
                if (w.w > tm.w) { tm.w = w.w; taw = c; }
            }

            int* sc = sconf[b & 1];
            atomicAdd(&sc[tax * NC + pax], 1);
            atomicAdd(&sc[tay * NC + pay], 1);
            atomicAdd(&sc[taz * NC + paz], 1);
            atomicAdd(&sc[taw * NC + paw], 1);
        }
    }

    __syncthreads();

    // Flush: map banks back to the (at most two) samples this block touched.
    const int b_lo = start >> 16;
    const int b_hi = (end - 1) >> 16;
    for (int i = threadIdx.x; i < NC2; i += TPB) {
        int v = sconf[b_lo & 1][i];
        if (v) atomicAdd(&g_conf[b_lo * NC2 + i], v);
        if (b_hi != b_lo) {
            int v2 = sconf[b_hi & 1][i];
            if (v2) atomicAdd(&g_conf[b_hi * NC2 + i], v2);
        }
    }

    // ---- last-block finalize ----
    __threadfence();
    __shared__ unsigned int s_rank;
    if (threadIdx.x == 0) s_rank = atomicAdd(&g_done, 1u);
    __syncthreads();
    if (s_rank != NBLOCKS - 1) return;

    __shared__ float iou_sum[NB];
    __shared__ int   valid_cnt[NB];
    int t = threadIdx.x;
    if (t < NB) { iou_sum[t] = 0.0f; valid_cnt[t] = 0; }
    if (t == 0) g_done = 0;                 // reset for next invocation
    __syncthreads();

    if (t < NB * NC) {
        int bb = t / NC;
        int c  = t - bb * NC;
        const int* cb = &g_conf[bb * NC2];
        int tpv = __ldcg(&cb[c * NC + c]);
        int row = 0, col = 0;
        #pragma unroll
        for (int k = 0; k < NC; k++) {
            row += __ldcg(&cb[c * NC + k]);   // TP + FN
            col += __ldcg(&cb[k * NC + c]);   // TP + FP
        }
        if (tpv > 0) {
            float iou = (float)tpv / (float)(row + col - tpv);
            atomicAdd(&iou_sum[bb], iou);
            atomicAdd(&valid_cnt[bb], 1);
        }
    }
    __syncthreads();

    // Re-zero scratch for the next invocation (all reads done above).
    for (int i = t; i < NB * NC2; i += TPB) g_conf[i] = 0;

    if (t == 0) {
        float s = 0.0f;
        #pragma unroll
        for (int bb = 0; bb < NB; bb++)
            s += iou_sum[bb] / fmaxf((float)valid_cnt[bb], 1.0f);
        out[0] = s / (float)NB;
    }
}

extern "C" void kernel_launch(void* const* d_in, const int* in_sizes, int n_in,
                              void* d_out, int out_size) {
    const float* pred = (const float*)d_in[0];
    const float* tgt  = (const float*)d_in[1];
    float* out = (float*)d_out;

    conf_kernel<<<NBLOCKS, TPB>>>(pred, tgt, out);
}